// round 14
// baseline (speedup 1.0000x reference)
#include <cuda_runtime.h>
#include <cuda_bf16.h>
#include <math.h>
#include <stdint.h>

#define B_ 4
#define N_ 1024
#define M_ 1024
#define D_ 512
#define EPS_ 0.1f
#define INV_EPS 10.0f
#define THRESH_ 0.1f
#define MAX_ITER_ 20
#define MU_CONST 0.0009765725f   /* 1/1024 + 1e-8 */
#define SAS 40                    /* smem row stride (bf16) for 32-wide k-chunk */
#define NB_LOOP 128               /* persistent loop grid (co-resident: < 148 SMs) */

// ---------------- device scratch (no allocation allowed) ----------------
__device__ __nv_bfloat16 g_E [(size_t)B_ * N_ * M_];  // exp(-C/eps) bf16
__device__ __nv_bfloat16 g_Et[(size_t)B_ * N_ * M_];  // transposed E bf16
__device__ __nv_bfloat16 g_xh[(size_t)B_ * N_ * D_];
__device__ __nv_bfloat16 g_yh[(size_t)B_ * M_ * D_];
__device__ float g_nx[B_ * N_];
__device__ float g_ny[B_ * M_];
__device__ float g_u [B_ * N_];   // u (for err metric)
__device__ float g_eu[B_ * N_];   // exp(u/eps)
__device__ float g_ev[B_ * M_];   // exp(v/eps)
__device__ float g_err[MAX_ITER_];
__device__ unsigned g_cnt;           // global barrier counter
__device__ unsigned g_gen;           // global barrier generation
__device__ unsigned g_cntb[B_];      // per-batch barrier counters
__device__ unsigned g_genb[B_];      // per-batch barrier generations

__device__ __forceinline__ uint32_t pack_bf2(float a, float b) {
    __nv_bfloat162 t = __floats2bfloat162_rn(a, b);
    return *(uint32_t*)&t;
}
__device__ __forceinline__ float2 b2f(uint32_t u) {
    __nv_bfloat162 h = *reinterpret_cast<__nv_bfloat162*>(&u);
    return __bfloat1622float2(h);
}

// ---------------------------------------------------------------------------
// fused: state init + norms + bf16 prep (xh, yh). 1024 blocks x 8 warps.
// ---------------------------------------------------------------------------
__global__ void k_prep(const float* __restrict__ X, const float* __restrict__ Y,
                       float* out) {
    int tid = threadIdx.x;
    if (blockIdx.x == 0) {
        for (int t = tid; t < B_ * N_; t += 256) { g_u[t] = 0.0f; g_eu[t] = 1.0f; }
        for (int t = tid; t < B_ * M_; t += 256) g_ev[t] = 1.0f;
        if (tid < MAX_ITER_) g_err[tid] = 0.0f;
        if (tid < B_) out[tid] = 0.0f;
    }
    int warp = tid >> 5, lane = tid & 31;
    int r = blockIdx.x * 8 + warp;          // 0..8191
    bool isx = r < B_ * N_;
    int rr = isx ? r : r - B_ * N_;
    const float4* s4 = (const float4*)((isx ? X : Y) + (size_t)rr * D_);
    float ss = 0.0f;
#pragma unroll
    for (int k = 0; k < 4; k++) {
        int idx = k * 32 + lane;
        float4 v = s4[idx];
        ss += v.x * v.x + v.y * v.y + v.z * v.z + v.w * v.w;
        uint2 hi;
        hi.x = pack_bf2(v.x, v.y);
        hi.y = pack_bf2(v.z, v.w);
        size_t e = (size_t)rr * D_ + idx * 4;
        if (isx) *(uint2*)&g_xh[e] = hi;
        else     *(uint2*)&g_yh[e] = hi;
    }
#pragma unroll
    for (int o = 16; o; o >>= 1) ss += __shfl_xor_sync(0xffffffffu, ss, o);
    if (lane == 0) {
        if (isx) g_nx[rr] = sqrtf(ss);
        else     g_ny[rr] = sqrtf(ss);
    }
}

// ---------------------------------------------------------------------------
__device__ __forceinline__ void ldsm4(uint32_t& r0, uint32_t& r1, uint32_t& r2,
                                      uint32_t& r3, uint32_t addr) {
    asm volatile("ldmatrix.sync.aligned.m8n8.x4.shared.b16 {%0,%1,%2,%3},[%4];"
                 : "=r"(r0), "=r"(r1), "=r"(r2), "=r"(r3) : "r"(addr));
}
__device__ __forceinline__ void mma_bf16(float* d, const uint32_t* a,
                                         uint32_t b0, uint32_t b1) {
    asm volatile(
        "mma.sync.aligned.m16n8k16.row.col.f32.bf16.bf16.f32 "
        "{%0,%1,%2,%3},{%4,%5,%6,%7},{%8,%9},{%0,%1,%2,%3};"
        : "+f"(d[0]), "+f"(d[1]), "+f"(d[2]), "+f"(d[3])
        : "r"(a[0]), "r"(a[1]), "r"(a[2]), "r"(a[3]), "r"(b0), "r"(b1));
}
__device__ __forceinline__ void cp16(uint32_t dst, const void* src) {
    asm volatile("cp.async.cg.shared.global [%0], [%1], 16;"
                 :: "r"(dst), "l"(src));
}

// 128x128 tile, 8 warps (2x4), warp tile 64x32, BK=32, cp.async double buffer.
// Epilogue: cos = dot/max(nx*ny,1e-8); E = exp(10*cos-10) -> g_E, g_Et (bf16).
__global__ __launch_bounds__(256, 2)
void k_gemm() {
    __shared__ __align__(16) char smem_raw[40960];
    uint32_t sbase = (uint32_t)__cvta_generic_to_shared(smem_raw);

    int b = blockIdx.z;
    int i0 = blockIdx.y * 128;
    int j0 = blockIdx.x * 128;
    int tid = threadIdx.x;
    int lane = tid & 31, warp = tid >> 5;
    int wm = warp >> 2, wn = warp & 3;

    const __nv_bfloat16* Ah = g_xh + (size_t)(b * N_ + i0) * D_;
    const __nv_bfloat16* Bp = g_yh + (size_t)(b * M_ + j0) * D_;

    // loader: per stage per matrix, 512 chunks of 8 bf16; 2 chunks/thread.
    int lrow = tid >> 1;                  // 0..127
    int lcol = (tid & 1) * 16;            // 0 or 16 (bf16 units), chunks +0,+8
    uint32_t sOffA = (uint32_t)(lrow * SAS + lcol) * 2;          // bytes
    uint32_t sOffB = sOffA + 10240;

    // ldmatrix per-lane offsets (bf16 units)
    int lr8 = lane & 7, seg = lane >> 3;
    int arow = (wm * 64 + lr8 + ((seg & 1) << 3)) * SAS + ((seg >> 1) << 3);
    int brow = (wn * 32 + lr8 + ((seg >> 1) << 3)) * SAS + ((seg & 1) << 3);

    float acc[4][4][4];
#pragma unroll
    for (int mi = 0; mi < 4; mi++)
#pragma unroll
        for (int nj = 0; nj < 4; nj++)
#pragma unroll
            for (int r = 0; r < 4; r++) acc[mi][nj][r] = 0.0f;

    const int STGB = 20480;   // stage stride bytes (A 10240 + B 10240)

    // issue stage 0
    {
        const __nv_bfloat16* a0 = Ah + (size_t)lrow * D_ + lcol;
        const __nv_bfloat16* b0 = Bp + (size_t)lrow * D_ + lcol;
        cp16(sbase + sOffA, a0);
        cp16(sbase + sOffA + 16, a0 + 8);
        cp16(sbase + sOffB, b0);
        cp16(sbase + sOffB + 16, b0 + 8);
        asm volatile("cp.async.commit_group;" ::: "memory");
    }

    for (int s = 0; s < 16; s++) {
        if (s + 1 < 16) {
            int k0 = (s + 1) * 32;
            int e = ((s + 1) & 1) * STGB;
            const __nv_bfloat16* a1 = Ah + (size_t)lrow * D_ + k0 + lcol;
            const __nv_bfloat16* b1 = Bp + (size_t)lrow * D_ + k0 + lcol;
            cp16(sbase + e + sOffA, a1);
            cp16(sbase + e + sOffA + 16, a1 + 8);
            cp16(sbase + e + sOffB, b1);
            cp16(sbase + e + sOffB + 16, b1 + 8);
            asm volatile("cp.async.commit_group;" ::: "memory");
            asm volatile("cp.async.wait_group 1;" ::: "memory");
        } else {
            asm volatile("cp.async.wait_group 0;" ::: "memory");
        }
        __syncthreads();

        uint32_t Sb = sbase + (s & 1) * STGB;
        uint32_t Bb = Sb + 10240;
#pragma unroll
        for (int kk = 0; kk < 32; kk += 16) {
            uint32_t bfr[2][4];
#pragma unroll
            for (int nt = 0; nt < 2; nt++)
                ldsm4(bfr[nt][0], bfr[nt][1], bfr[nt][2], bfr[nt][3],
                      Bb + (uint32_t)(brow + nt * 16 * SAS + kk) * 2);
            uint32_t a[4][4];
#pragma unroll
            for (int mi = 0; mi < 4; mi++)
                ldsm4(a[mi][0], a[mi][1], a[mi][2], a[mi][3],
                      Sb + (uint32_t)(arow + mi * 16 * SAS + kk) * 2);
#pragma unroll
            for (int mi = 0; mi < 4; mi++)
#pragma unroll
                for (int nj = 0; nj < 4; nj++)
                    mma_bf16(acc[mi][nj], a[mi],
                             bfr[nj >> 1][(nj & 1) * 2], bfr[nj >> 1][(nj & 1) * 2 + 1]);
        }
        __syncthreads();
    }

    // -------- epilogue: stage dot values half-tile at a time --------
    float* stg = (float*)smem_raw;   // 64 x (stride 132) floats = 33792 B (fits)
    const int ST = 132;
    size_t bN = (size_t)b * N_, bM = (size_t)b * M_;
    for (int h = 0; h < 2; h++) {
        __syncthreads();
        if (wm == h) {
#pragma unroll
            for (int mi = 0; mi < 4; mi++)
#pragma unroll
                for (int nj = 0; nj < 4; nj++) {
                    int rr = mi * 16 + (lane >> 2);
                    int cc = wn * 32 + nj * 8 + (lane & 3) * 2;
                    stg[rr * ST + cc]           = acc[mi][nj][0];
                    stg[rr * ST + cc + 1]       = acc[mi][nj][1];
                    stg[(rr + 8) * ST + cc]     = acc[mi][nj][2];
                    stg[(rr + 8) * ST + cc + 1] = acc[mi][nj][3];
                }
        }
        __syncthreads();
#pragma unroll
        for (int q = 0; q < 8; q++) {
            int idx = tid + q * 256;
            int r = idx >> 5, cg = (idx & 31) * 4;
            int gi = i0 + h * 64 + r, gj = j0 + cg;
            float nxv = g_nx[bN + gi];
            float4 ny4 = *(const float4*)&g_ny[bM + gj];
            float4 dt = *(const float4*)&stg[r * ST + cg];
            float e0 = __expf(INV_EPS * dt.x / fmaxf(nxv * ny4.x, 1e-8f) - INV_EPS);
            float e1 = __expf(INV_EPS * dt.y / fmaxf(nxv * ny4.y, 1e-8f) - INV_EPS);
            float e2 = __expf(INV_EPS * dt.z / fmaxf(nxv * ny4.z, 1e-8f) - INV_EPS);
            float e3 = __expf(INV_EPS * dt.w / fmaxf(nxv * ny4.w, 1e-8f) - INV_EPS);
            uint2 p;
            p.x = pack_bf2(e0, e1);
            p.y = pack_bf2(e2, e3);
            *(uint2*)&g_E[(bN + gi) * (size_t)M_ + gj] = p;
        }
#pragma unroll
        for (int q = 0; q < 8; q++) {
            int idx = tid + q * 256;
            int jr = idx >> 4, ig = (idx & 15) * 4;
            int gj = j0 + jr;
            int gi0 = i0 + h * 64 + ig;
            float nyv = g_ny[bM + gj];
            float4 nx4 = *(const float4*)&g_nx[bN + gi0];
            float d0 = stg[(ig + 0) * ST + jr];
            float d1 = stg[(ig + 1) * ST + jr];
            float d2 = stg[(ig + 2) * ST + jr];
            float d3 = stg[(ig + 3) * ST + jr];
            float e0 = __expf(INV_EPS * d0 / fmaxf(nx4.x * nyv, 1e-8f) - INV_EPS);
            float e1 = __expf(INV_EPS * d1 / fmaxf(nx4.y * nyv, 1e-8f) - INV_EPS);
            float e2 = __expf(INV_EPS * d2 / fmaxf(nx4.z * nyv, 1e-8f) - INV_EPS);
            float e3 = __expf(INV_EPS * d3 / fmaxf(nx4.w * nyv, 1e-8f) - INV_EPS);
            uint2 p;
            p.x = pack_bf2(e0, e1);
            p.y = pack_bf2(e2, e3);
            *(uint2*)&g_Et[(bM + gj) * (size_t)N_ + gi0] = p;
        }
    }
}

// ---------------------------------------------------------------------------
// barriers
// ---------------------------------------------------------------------------
__device__ __forceinline__ void bar_sync(unsigned* cnt, unsigned* gen, unsigned nb) {
    __syncthreads();
    if (threadIdx.x == 0) {
        unsigned my = *((volatile unsigned*)gen);
        __threadfence();
        unsigned old = atomicAdd(cnt, 1u);
        if (old == nb - 1) {
            atomicExch(cnt, 0u);
            __threadfence();
            atomicAdd(gen, 1u);
        } else {
            while (*((volatile unsigned*)gen) == my) __nanosleep(32);
        }
    }
    __syncthreads();
}

// dual-row GEMV over bf16 rows of length 1024 against smem vec (MLP=8)
__device__ __forceinline__ void row_dot2(const uint4* __restrict__ E0,
                                         const uint4* __restrict__ E1,
                                         const float4* __restrict__ v4,
                                         int lane, float& s0o, float& s1o) {
    float s0 = 0.0f, s1 = 0.0f;
#pragma unroll
    for (int k = 0; k < 4; k++) {
        int c = k * 32 + lane;
        uint4 q0 = E0[c];
        uint4 q1 = E1[c];
        float4 w0 = v4[c * 2];
        float4 w1 = v4[c * 2 + 1];
        float2 a0, a1, a2, a3;
        a0 = b2f(q0.x); a1 = b2f(q0.y); a2 = b2f(q0.z); a3 = b2f(q0.w);
        s0 += a0.x * w0.x + a0.y * w0.y + a1.x * w0.z + a1.y * w0.w;
        s0 += a2.x * w1.x + a2.y * w1.y + a3.x * w1.z + a3.y * w1.w;
        a0 = b2f(q1.x); a1 = b2f(q1.y); a2 = b2f(q1.z); a3 = b2f(q1.w);
        s1 += a0.x * w0.x + a0.y * w0.y + a1.x * w0.z + a1.y * w0.w;
        s1 += a2.x * w1.x + a2.y * w1.y + a3.x * w1.z + a3.y * w1.w;
    }
#pragma unroll
    for (int o = 16; o; o >>= 1) {
        s0 += __shfl_xor_sync(0xffffffffu, s0, o);
        s1 += __shfl_xor_sync(0xffffffffu, s1, o);
    }
    s0o = s0; s1o = s1;
}

// ---------------------------------------------------------------------------
// persistent Sinkhorn loop + cost. Grid = NB_LOOP blocks (co-resident).
// block: batch b = blk>>5, rows [(blk&31)*32, +32). 4 rows/warp (2x2 pairs).
// ---------------------------------------------------------------------------
__global__ __launch_bounds__(256, 2)
void k_loop(const float* __restrict__ nu, float* out) {
    __shared__ __align__(16) float svec[1024];
    __shared__ float serr;
    int tid = threadIdx.x;
    int b = blockIdx.x >> 5;
    int r0 = (blockIdx.x & 31) << 5;
    int warp = tid >> 5, lane = tid & 31;
    const float4* v4 = (const float4*)svec;

    for (int it = 0; it < MAX_ITER_; ++it) {
        // ---- row phase: u update ----
        ((float4*)svec)[tid] = ((const float4*)&g_ev[b * M_])[tid];
        if (tid == 0) serr = 0.0f;
        __syncthreads();
        float dloc = 0.0f;
#pragma unroll
        for (int rp = 0; rp < 2; rp++) {
            int i = r0 + rp * 16 + warp;
            float s0, s1;
            row_dot2((const uint4*)(g_E + ((size_t)(b * N_ + i)) * M_),
                     (const uint4*)(g_E + ((size_t)(b * N_ + i + 8)) * M_),
                     v4, lane, s0, s1);
            if (lane == 0) {
                int idx = b * N_ + i;
                float eu0 = MU_CONST / s0;
                float un0 = EPS_ * __logf(eu0);
                dloc += fabsf(un0 - g_u[idx]);
                g_u[idx] = un0; g_eu[idx] = eu0;
                float eu1 = MU_CONST / s1;
                float un1 = EPS_ * __logf(eu1);
                dloc += fabsf(un1 - g_u[idx + 8]);
                g_u[idx + 8] = un1; g_eu[idx + 8] = eu1;
            }
        }
        if (lane == 0) atomicAdd(&serr, dloc);
        __syncthreads();
        if (tid == 0) atomicAdd(&g_err[it], serr);
        bar_sync(&g_cnt, &g_gen, NB_LOOP);            // GLOBAL (err complete)

        // ---- col phase: v update ----
        ((float4*)svec)[tid] = ((const float4*)&g_eu[b * N_])[tid];
        __syncthreads();
#pragma unroll
        for (int rp = 0; rp < 2; rp++) {
            int j = r0 + rp * 16 + warp;
            float s0, s1;
            row_dot2((const uint4*)(g_Et + ((size_t)(b * M_ + j)) * N_),
                     (const uint4*)(g_Et + ((size_t)(b * M_ + j + 8)) * N_),
                     v4, lane, s0, s1);
            if (lane == 0) {
                g_ev[b * M_ + j]     = (nu[b * M_ + j] + 1e-8f) / s0;
                g_ev[b * M_ + j + 8] = (nu[b * M_ + j + 8] + 1e-8f) / s1;
            }
        }
        bar_sync(&g_cntb[b], &g_genb[b], 32u);        // per-batch (ev[b] ready)

        // convergence (g_err[it] globally complete since the row barrier)
        if (g_err[it] < THRESH_ * (float)B_) break;
    }

    // ---- cost: cost[b] = sum_ij eu_i*ev_j*E_ij*(-eps*ln E_ij) ----
    ((float4*)svec)[tid] = ((const float4*)&g_ev[b * M_])[tid];
    if (tid == 0) serr = 0.0f;
    __syncthreads();
    float tot = 0.0f;
#pragma unroll
    for (int rp = 0; rp < 2; rp++) {
        int i = r0 + rp * 16 + warp;
        const uint4* E0 = (const uint4*)(g_E + ((size_t)(b * N_ + i)) * M_);
        const uint4* E1 = (const uint4*)(g_E + ((size_t)(b * N_ + i + 8)) * M_);
        float s0 = 0.0f, s1 = 0.0f;
#pragma unroll
        for (int k = 0; k < 4; k++) {
            int c = k * 32 + lane;
            uint4 q0 = E0[c];
            uint4 q1 = E1[c];
            float4 w0 = v4[c * 2];
            float4 w1 = v4[c * 2 + 1];
            float2 a0, a1, a2, a3;
            a0 = b2f(q0.x); a1 = b2f(q0.y); a2 = b2f(q0.z); a3 = b2f(q0.w);
            s0 += a0.x * w0.x * __logf(a0.x) + a0.y * w0.y * __logf(a0.y);
            s0 += a1.x * w0.z * __logf(a1.x) + a1.y * w0.w * __logf(a1.y);
            s0 += a2.x * w1.x * __logf(a2.x) + a2.y * w1.y * __logf(a2.y);
            s0 += a3.x * w1.z * __logf(a3.x) + a3.y * w1.w * __logf(a3.y);
            a0 = b2f(q1.x); a1 = b2f(q1.y); a2 = b2f(q1.z); a3 = b2f(q1.w);
            s1 += a0.x * w0.x * __logf(a0.x) + a0.y * w0.y * __logf(a0.y);
            s1 += a1.x * w0.z * __logf(a1.x) + a1.y * w0.w * __logf(a1.y);
            s1 += a2.x * w1.x * __logf(a2.x) + a2.y * w1.y * __logf(a2.y);
            s1 += a3.x * w1.z * __logf(a3.x) + a3.y * w1.w * __logf(a3.y);
        }
#pragma unroll
        for (int o = 16; o; o >>= 1) {
            s0 += __shfl_xor_sync(0xffffffffu, s0, o);
            s1 += __shfl_xor_sync(0xffffffffu, s1, o);
        }
        if (lane == 0)
            tot += -EPS_ * (g_eu[b * N_ + i] * s0 + g_eu[b * N_ + i + 8] * s1);
    }
    if (lane == 0) atomicAdd(&serr, tot);
    __syncthreads();
    if (tid == 0) atomicAdd(&out[b], serr);
}

// ---------------------------------------------------------------------------
extern "C" void kernel_launch(void* const* d_in, const int* in_sizes, int n_in,
                              void* d_out, int out_size) {
    (void)in_sizes; (void)n_in; (void)out_size;
    const float* x  = (const float*)d_in[0];
    const float* y  = (const float*)d_in[1];
    const float* nu = (const float*)d_in[2];
    float* out = (float*)d_out;

    k_prep<<<1024, 256>>>(x, y, out);
    k_gemm<<<dim3(8, 8, B_), 256>>>();
    k_loop<<<NB_LOOP, 256>>>(nu, out);
}

// round 16
// speedup vs baseline: 1.1921x; 1.1921x over previous
#include <cuda_runtime.h>
#include <cuda_bf16.h>
#include <cuda_fp16.h>
#include <math.h>
#include <stdint.h>

#define B_ 4
#define N_ 1024
#define M_ 1024
#define D_ 512
#define EPS_ 0.1f
#define INV_EPS 10.0f
#define THRESH_ 0.1f
#define MAX_ITER_ 20
#define MU_CONST 0.0009765725f   /* 1/1024 + 1e-8 */
#define SAS 24                    /* smem row stride (bf16) for 16-wide k-chunk */
#define NB_LOOP 128               /* persistent loop grid (co-resident: < 148 SMs) */
#define QSC 256.0f                /* cos scale for fp8 storage */
#define QINV 0.00390625f          /* 1/256 */

// ---------------- device scratch (no allocation allowed) ----------------
__device__ __nv_bfloat16 g_E [(size_t)B_ * N_ * M_];  // exp(-C/eps) bf16
__device__ __nv_bfloat16 g_Et[(size_t)B_ * N_ * M_];  // transposed E bf16
__device__ uint8_t g_Q [(size_t)B_ * N_ * M_];        // fp8 e4m3: cos*256, row-major
__device__ __nv_bfloat16 g_xh[(size_t)B_ * N_ * D_];
__device__ __nv_bfloat16 g_yh[(size_t)B_ * M_ * D_];
__device__ float g_nx[B_ * N_];
__device__ float g_ny[B_ * M_];
__device__ float g_u [B_ * N_];   // u (for err metric)
__device__ float g_eu[B_ * N_];   // exp(u/eps)
__device__ float g_ev[B_ * M_];   // exp(v/eps)
__device__ float g_err[MAX_ITER_];
__device__ unsigned g_cnt;           // global barrier counter
__device__ unsigned g_gen;           // global barrier generation
__device__ unsigned g_cntb[B_];      // per-batch barrier counters
__device__ unsigned g_genb[B_];      // per-batch barrier generations

__device__ __forceinline__ uint32_t pack_bf2(float a, float b) {
    __nv_bfloat162 t = __floats2bfloat162_rn(a, b);
    return *(uint32_t*)&t;
}
__device__ __forceinline__ float2 b2f(uint32_t u) {
    __nv_bfloat162 h = *reinterpret_cast<__nv_bfloat162*>(&u);
    return __bfloat1622float2(h);
}
// pack 4 floats to 4 fp8 e4m3 (byte0 = f0)
__device__ __forceinline__ uint32_t pack_fp8x4(float f0, float f1, float f2, float f3) {
    uint16_t lo, hi;
    asm("cvt.rn.satfinite.e4m3x2.f32 %0, %1, %2;" : "=h"(lo) : "f"(f1), "f"(f0));
    asm("cvt.rn.satfinite.e4m3x2.f32 %0, %1, %2;" : "=h"(hi) : "f"(f3), "f"(f2));
    return (uint32_t)lo | ((uint32_t)hi << 16);
}
// unpack 4 fp8 e4m3 -> float4 (element0 = byte0)
__device__ __forceinline__ float4 fp8x4_to_f4(uint32_t w) {
    uint32_t h0, h1;
    asm("{\n\t.reg .b16 lo, hi;\n\t"
        "mov.b32 {lo, hi}, %2;\n\t"
        "cvt.rn.f16x2.e4m3x2 %0, lo;\n\t"
        "cvt.rn.f16x2.e4m3x2 %1, hi;\n\t}"
        : "=r"(h0), "=r"(h1) : "r"(w));
    float2 a = __half22float2(*reinterpret_cast<__half2*>(&h0));
    float2 b = __half22float2(*reinterpret_cast<__half2*>(&h1));
    return make_float4(a.x, a.y, b.x, b.y);
}

// ---------------------------------------------------------------------------
// fused: state init + norms + bf16 prep (xh, yh). 1024 blocks x 8 warps.
// ---------------------------------------------------------------------------
__global__ void k_prep(const float* __restrict__ X, const float* __restrict__ Y,
                       float* out) {
    int tid = threadIdx.x;
    if (blockIdx.x == 0) {
        for (int t = tid; t < B_ * N_; t += 256) { g_u[t] = 0.0f; g_eu[t] = 1.0f; }
        for (int t = tid; t < B_ * M_; t += 256) g_ev[t] = 1.0f;
        if (tid < MAX_ITER_) g_err[tid] = 0.0f;
        if (tid < B_) out[tid] = 0.0f;
    }
    int warp = tid >> 5, lane = tid & 31;
    int r = blockIdx.x * 8 + warp;          // 0..8191
    bool isx = r < B_ * N_;
    int rr = isx ? r : r - B_ * N_;
    const float4* s4 = (const float4*)((isx ? X : Y) + (size_t)rr * D_);
    float ss = 0.0f;
#pragma unroll
    for (int k = 0; k < 4; k++) {
        int idx = k * 32 + lane;
        float4 v = s4[idx];
        ss += v.x * v.x + v.y * v.y + v.z * v.z + v.w * v.w;
        uint2 hi;
        hi.x = pack_bf2(v.x, v.y);
        hi.y = pack_bf2(v.z, v.w);
        size_t e = (size_t)rr * D_ + idx * 4;
        if (isx) *(uint2*)&g_xh[e] = hi;
        else     *(uint2*)&g_yh[e] = hi;
    }
#pragma unroll
    for (int o = 16; o; o >>= 1) ss += __shfl_xor_sync(0xffffffffu, ss, o);
    if (lane == 0) {
        if (isx) g_nx[rr] = sqrtf(ss);
        else     g_ny[rr] = sqrtf(ss);
    }
}

// ---------------------------------------------------------------------------
__device__ __forceinline__ void ldsm4(uint32_t& r0, uint32_t& r1, uint32_t& r2,
                                      uint32_t& r3, uint32_t addr) {
    asm volatile("ldmatrix.sync.aligned.m8n8.x4.shared.b16 {%0,%1,%2,%3},[%4];"
                 : "=r"(r0), "=r"(r1), "=r"(r2), "=r"(r3) : "r"(addr));
}
__device__ __forceinline__ void mma_bf16(float* d, const uint32_t* a,
                                         uint32_t b0, uint32_t b1) {
    asm volatile(
        "mma.sync.aligned.m16n8k16.row.col.f32.bf16.bf16.f32 "
        "{%0,%1,%2,%3},{%4,%5,%6,%7},{%8,%9},{%0,%1,%2,%3};"
        : "+f"(d[0]), "+f"(d[1]), "+f"(d[2]), "+f"(d[3])
        : "r"(a[0]), "r"(a[1]), "r"(a[2]), "r"(a[3]), "r"(b0), "r"(b1));
}

// 128x128 tile, 8 warps (2x4), warp tile 64x32, BK=16, single xh*yh pass.
// Epilogue: cos = dot/max(nx*ny,1e-8); E = exp(10*cos-10) -> g_E, g_Et (bf16);
//           Q = cos*256 (fp8 e4m3) row-major for log-free cost.
__global__ __launch_bounds__(256, 2)
void k_gemm() {
    __shared__ __align__(16) char smem_raw[36864];
    __nv_bfloat16* sAB = (__nv_bfloat16*)smem_raw;
    uint32_t sbase = (uint32_t)__cvta_generic_to_shared(smem_raw);

    int b = blockIdx.z;
    int i0 = blockIdx.y * 128;
    int j0 = blockIdx.x * 128;
    int tid = threadIdx.x;
    int lane = tid & 31, warp = tid >> 5;
    int wm = warp >> 2, wn = warp & 3;

    const __nv_bfloat16* Ah = g_xh + (size_t)(b * N_ + i0) * D_;
    const __nv_bfloat16* Bp = g_yh + (size_t)(b * M_ + j0) * D_;

    int lr = tid >> 1;
    int lcH = (tid & 1) * 8;
    int sIdx = lr * SAS + lcH;

    int lr8 = lane & 7, seg = lane >> 3;
    int arow = (wm * 64 + lr8 + ((seg & 1) << 3)) * SAS + ((seg >> 1) << 3);
    int brow = (wn * 32 + lr8 + ((seg >> 1) << 3)) * SAS + ((seg & 1) << 3);

    float acc[4][4][4];
#pragma unroll
    for (int mi = 0; mi < 4; mi++)
#pragma unroll
        for (int nj = 0; nj < 4; nj++)
#pragma unroll
            for (int r = 0; r < 4; r++) acc[mi][nj][r] = 0.0f;

    const int STG = 6144;    // stage stride in bf16 ELEMENTS
    const int MATB = 3072;   // per-matrix stride in bf16 elements

    float4 fa, fb;
    fa = *(const float4*)(Ah + lr * D_ + lcH);
    fb = *(const float4*)(Bp + lr * D_ + lcH);
    *(float4*)&sAB[sIdx]        = fa;
    *(float4*)&sAB[MATB + sIdx] = fb;
    __syncthreads();

    for (int s = 0; s < 32; s++) {
        int buf = s & 1;
        if (s + 1 < 32) {
            int k0 = (s + 1) * 16;
            fa = *(const float4*)(Ah + lr * D_ + k0 + lcH);
            fb = *(const float4*)(Bp + lr * D_ + k0 + lcH);
        }
        uint32_t Sb = sbase + buf * (STG * 2);
        uint32_t Bb = Sb + MATB * 2;
        uint32_t bfr[2][4];
#pragma unroll
        for (int nt = 0; nt < 2; nt++)
            ldsm4(bfr[nt][0], bfr[nt][1], bfr[nt][2], bfr[nt][3],
                  Bb + (uint32_t)(brow + nt * 16 * SAS) * 2);
        {
            uint32_t a[4][4];
#pragma unroll
            for (int mi = 0; mi < 4; mi++)
                ldsm4(a[mi][0], a[mi][1], a[mi][2], a[mi][3],
                      Sb + (uint32_t)(arow + mi * 16 * SAS) * 2);
#pragma unroll
            for (int mi = 0; mi < 4; mi++)
#pragma unroll
                for (int nj = 0; nj < 4; nj++)
                    mma_bf16(acc[mi][nj], a[mi],
                             bfr[nj >> 1][(nj & 1) * 2], bfr[nj >> 1][(nj & 1) * 2 + 1]);
        }
        if (s + 1 < 32) {
            int e = ((s + 1) & 1) * STG;
            *(float4*)&sAB[e + sIdx]        = fa;
            *(float4*)&sAB[e + MATB + sIdx] = fb;
        }
        __syncthreads();
    }

    // -------- epilogue: stage dot values half-tile at a time --------
    float* stg = (float*)smem_raw;
    const int ST = 132;
    size_t bN = (size_t)b * N_, bM = (size_t)b * M_;
    for (int h = 0; h < 2; h++) {
        __syncthreads();
        if (wm == h) {
#pragma unroll
            for (int mi = 0; mi < 4; mi++)
#pragma unroll
                for (int nj = 0; nj < 4; nj++) {
                    int rr = mi * 16 + (lane >> 2);
                    int cc = wn * 32 + nj * 8 + (lane & 3) * 2;
                    stg[rr * ST + cc]           = acc[mi][nj][0];
                    stg[rr * ST + cc + 1]       = acc[mi][nj][1];
                    stg[(rr + 8) * ST + cc]     = acc[mi][nj][2];
                    stg[(rr + 8) * ST + cc + 1] = acc[mi][nj][3];
                }
        }
        __syncthreads();
        // row-order outputs: E bf16 + Q fp8
#pragma unroll
        for (int q = 0; q < 8; q++) {
            int idx = tid + q * 256;
            int r = idx >> 5, cg = (idx & 31) * 4;
            int gi = i0 + h * 64 + r, gj = j0 + cg;
            float nxv = g_nx[bN + gi];
            float4 ny4 = *(const float4*)&g_ny[bM + gj];
            float4 dt = *(const float4*)&stg[r * ST + cg];
            float c0 = dt.x / fmaxf(nxv * ny4.x, 1e-8f);
            float c1 = dt.y / fmaxf(nxv * ny4.y, 1e-8f);
            float c2 = dt.z / fmaxf(nxv * ny4.z, 1e-8f);
            float c3 = dt.w / fmaxf(nxv * ny4.w, 1e-8f);
            float e0 = __expf(INV_EPS * c0 - INV_EPS);
            float e1 = __expf(INV_EPS * c1 - INV_EPS);
            float e2 = __expf(INV_EPS * c2 - INV_EPS);
            float e3 = __expf(INV_EPS * c3 - INV_EPS);
            size_t off = (bN + gi) * (size_t)M_ + gj;
            uint2 p;
            p.x = pack_bf2(e0, e1);
            p.y = pack_bf2(e2, e3);
            *(uint2*)&g_E[off] = p;
            *(uint32_t*)&g_Q[off] =
                pack_fp8x4(c0 * QSC, c1 * QSC, c2 * QSC, c3 * QSC);
        }
        // transposed outputs: Et bf16
#pragma unroll
        for (int q = 0; q < 8; q++) {
            int idx = tid + q * 256;
            int jr = idx >> 4, ig = (idx & 15) * 4;
            int gj = j0 + jr;
            int gi0 = i0 + h * 64 + ig;
            float nyv = g_ny[bM + gj];
            float4 nx4 = *(const float4*)&g_nx[bN + gi0];
            float d0 = stg[(ig + 0) * ST + jr];
            float d1 = stg[(ig + 1) * ST + jr];
            float d2 = stg[(ig + 2) * ST + jr];
            float d3 = stg[(ig + 3) * ST + jr];
            float e0 = __expf(INV_EPS * d0 / fmaxf(nx4.x * nyv, 1e-8f) - INV_EPS);
            float e1 = __expf(INV_EPS * d1 / fmaxf(nx4.y * nyv, 1e-8f) - INV_EPS);
            float e2 = __expf(INV_EPS * d2 / fmaxf(nx4.z * nyv, 1e-8f) - INV_EPS);
            float e3 = __expf(INV_EPS * d3 / fmaxf(nx4.w * nyv, 1e-8f) - INV_EPS);
            uint2 p;
            p.x = pack_bf2(e0, e1);
            p.y = pack_bf2(e2, e3);
            *(uint2*)&g_Et[(bM + gj) * (size_t)N_ + gi0] = p;
        }
    }
}

// ---------------------------------------------------------------------------
// barriers
// ---------------------------------------------------------------------------
__device__ __forceinline__ void bar_sync(unsigned* cnt, unsigned* gen, unsigned nb) {
    __syncthreads();
    if (threadIdx.x == 0) {
        unsigned my = *((volatile unsigned*)gen);
        __threadfence();
        unsigned old = atomicAdd(cnt, 1u);
        if (old == nb - 1) {
            atomicExch(cnt, 0u);
            __threadfence();
            atomicAdd(gen, 1u);
        } else {
            while (*((volatile unsigned*)gen) == my) __nanosleep(32);
        }
    }
    __syncthreads();
}

// warp-level GEMV over one bf16 row of length 1024 against smem vec
__device__ __forceinline__ float row_dot(const uint4* __restrict__ Er,
                                         const float4* __restrict__ v4, int lane) {
    float s = 0.0f;
#pragma unroll
    for (int k = 0; k < 4; k++) {
        int c = k * 32 + lane;
        uint4 q = Er[c];
        float4 w0 = v4[c * 2];
        float4 w1 = v4[c * 2 + 1];
        float2 a0 = b2f(q.x), a1 = b2f(q.y), a2 = b2f(q.z), a3 = b2f(q.w);
        s += a0.x * w0.x + a0.y * w0.y + a1.x * w0.z + a1.y * w0.w;
        s += a2.x * w1.x + a2.y * w1.y + a3.x * w1.z + a3.y * w1.w;
    }
#pragma unroll
    for (int o = 16; o; o >>= 1) s += __shfl_xor_sync(0xffffffffu, s, o);
    return s;
}

// ---------------------------------------------------------------------------
// persistent Sinkhorn loop + log-free cost. Grid = NB_LOOP blocks.
// block: batch b = blk>>5, rows [(blk&31)*32, +32). 4 rows/warp.
// ---------------------------------------------------------------------------
__global__ __launch_bounds__(256, 2)
void k_loop(const float* __restrict__ nu, float* out) {
    __shared__ __align__(16) float svec[1024];
    __shared__ float serr;
    __shared__ float snu;
    int tid = threadIdx.x;
    int b = blockIdx.x >> 5;
    int r0 = (blockIdx.x & 31) << 5;
    int warp = tid >> 5, lane = tid & 31;
    const float4* v4 = (const float4*)svec;

    for (int it = 0; it < MAX_ITER_; ++it) {
        // ---- row phase: u update ----
        ((float4*)svec)[tid] = ((const float4*)&g_ev[b * M_])[tid];
        if (tid == 0) serr = 0.0f;
        __syncthreads();
        float dloc = 0.0f;
#pragma unroll
        for (int ri = 0; ri < 4; ri++) {
            int i = r0 + ri * 8 + warp;
            float s = row_dot((const uint4*)(g_E + ((size_t)(b * N_ + i)) * M_), v4, lane);
            if (lane == 0) {
                int idx = b * N_ + i;
                float eu_new = MU_CONST / s;
                float unew = EPS_ * __logf(eu_new);
                dloc += fabsf(unew - g_u[idx]);
                g_u[idx] = unew;
                g_eu[idx] = eu_new;
            }
        }
        if (lane == 0) atomicAdd(&serr, dloc);
        __syncthreads();
        if (tid == 0) atomicAdd(&g_err[it], serr);
        bar_sync(&g_cnt, &g_gen, NB_LOOP);            // GLOBAL (err + eu complete)

        // ---- col phase: v update ----
        ((float4*)svec)[tid] = ((const float4*)&g_eu[b * N_])[tid];
        __syncthreads();
#pragma unroll
        for (int ri = 0; ri < 4; ri++) {
            int j = r0 + ri * 8 + warp;
            float s = row_dot((const uint4*)(g_Et + ((size_t)(b * M_ + j)) * N_), v4, lane);
            if (lane == 0)
                g_ev[b * M_ + j] = (nu[b * M_ + j] + 1e-8f) / s;
        }
        bar_sync(&g_cntb[b], &g_genb[b], 32u);        // per-batch (ev[b] ready)

        // convergence (g_err[it] globally complete since the row barrier)
        if (g_err[it] < THRESH_ * (float)B_) break;
    }

    // ---- cost (log-free): cost[b] = sum(nu+1e-8) - (1/256)*sum eu ev E Q ----
    ((float4*)svec)[tid] = ((const float4*)&g_ev[b * M_])[tid];
    if (tid == 0) { serr = 0.0f; snu = 0.0f; }
    __syncthreads();

    // one block per batch computes sum(nu + 1e-8) = Sigma pi (exact identity)
    if ((blockIdx.x & 31) == 0) {
        float4 nv = ((const float4*)&nu[b * M_])[tid];
        float t = nv.x + nv.y + nv.z + nv.w + 4e-8f;
#pragma unroll
        for (int o = 16; o; o >>= 1) t += __shfl_xor_sync(0xffffffffu, t, o);
        if (lane == 0) atomicAdd(&snu, t);
    }

    float tot = 0.0f;
#pragma unroll
    for (int ri = 0; ri < 4; ri++) {
        int i = r0 + ri * 8 + warp;
        size_t off = ((size_t)(b * N_ + i)) * M_;
        const uint4* Er = (const uint4*)(g_E + off);
        const uint2* Qr = (const uint2*)(g_Q + off);
        float s = 0.0f;
#pragma unroll
        for (int k = 0; k < 4; k++) {
            int c = k * 32 + lane;
            uint4 q = Er[c];
            uint2 qq = Qr[c];
            float4 w0 = v4[c * 2];
            float4 w1 = v4[c * 2 + 1];
            float2 a0 = b2f(q.x), a1 = b2f(q.y), a2 = b2f(q.z), a3 = b2f(q.w);
            float4 g0 = fp8x4_to_f4(qq.x);
            float4 g1 = fp8x4_to_f4(qq.y);
            s += a0.x * g0.x * w0.x + a0.y * g0.y * w0.y;
            s += a1.x * g0.z * w0.z + a1.y * g0.w * w0.w;
            s += a2.x * g1.x * w1.x + a2.y * g1.y * w1.y;
            s += a3.x * g1.z * w1.z + a3.y * g1.w * w1.w;
        }
#pragma unroll
        for (int o = 16; o; o >>= 1) s += __shfl_xor_sync(0xffffffffu, s, o);
        if (lane == 0) tot += g_eu[b * N_ + i] * s;
    }
    if (lane == 0) atomicAdd(&serr, tot);
    __syncthreads();
    if (tid == 0) atomicAdd(&out[b], snu - serr * QINV);
}

// ---------------------------------------------------------------------------
extern "C" void kernel_launch(void* const* d_in, const int* in_sizes, int n_in,
                              void* d_out, int out_size) {
    (void)in_sizes; (void)n_in; (void)out_size;
    const float* x  = (const float*)d_in[0];
    const float* y  = (const float*)d_in[1];
    const float* nu = (const float*)d_in[2];
    float* out = (float*)d_out;

    k_prep<<<1024, 256>>>(x, y, out);
    k_gemm<<<dim3(8, 8, B_), 256>>>();
    k_loop<<<NB_LOOP, 256>>>(nu, out);
}